// round 6
// baseline (speedup 1.0000x reference)
#include <cuda_runtime.h>
#include <cstdint>

// Embedding gather: out[i, :] = weight[indices[i], :]
// 819200 rows x 64 fp32 = 256B/row. 8 threads cover one row with 256-bit ops.
// v6: UNROLL=8 front-batched (256B in flight per thread) to raise DRAM
// utilization past 74%; 256-bit gathers evict_last, 256-bit stores evict_first.

static constexpr int UNROLL = 8;

struct V8 { uint32_t r[8]; };

__device__ __forceinline__ V8 ldg256_evict_last(const uint32_t* p) {
    V8 v;
    asm volatile("ld.global.nc.L2::evict_last.v8.b32 {%0,%1,%2,%3,%4,%5,%6,%7}, [%8];"
                 : "=r"(v.r[0]), "=r"(v.r[1]), "=r"(v.r[2]), "=r"(v.r[3]),
                   "=r"(v.r[4]), "=r"(v.r[5]), "=r"(v.r[6]), "=r"(v.r[7])
                 : "l"(p));
    return v;
}

__device__ __forceinline__ void stg256_evict_first(uint32_t* p, const V8& v) {
    asm volatile("st.global.L2::evict_first.v8.b32 [%0], {%1,%2,%3,%4,%5,%6,%7,%8};"
                 :: "l"(p),
                    "r"(v.r[0]), "r"(v.r[1]), "r"(v.r[2]), "r"(v.r[3]),
                    "r"(v.r[4]), "r"(v.r[5]), "r"(v.r[6]), "r"(v.r[7]));
}

// Exact path: total 32B-segments divisible by blockDim*UNROLL.
__global__ __launch_bounds__(512)
void embed_gather_exact(const int* __restrict__ indices,
                        const uint32_t* __restrict__ weight,
                        uint32_t* __restrict__ out)
{
    const long long stride     = (long long)gridDim.x * blockDim.x; // mult of 8
    const long long base       = (long long)blockIdx.x * blockDim.x + threadIdx.x;
    const int       seg        = (int)(base & 7);      // 32B segment within row
    const long long row0       = base >> 3;
    const long long row_stride = stride >> 3;

    // Batch 1: independent index loads
    int idx[UNROLL];
#pragma unroll
    for (int k = 0; k < UNROLL; k++)
        idx[k] = __ldg(indices + row0 + (long long)k * row_stride);

    // Batch 2: 8 independent 256-bit gathers in flight per thread
    V8 v[UNROLL];
#pragma unroll
    for (int k = 0; k < UNROLL; k++)
        v[k] = ldg256_evict_last(weight + (long long)idx[k] * 64 + seg * 8);

    // Batch 3: 256-bit streaming stores, evict-first
#pragma unroll
    for (int k = 0; k < UNROLL; k++)
        stg256_evict_first(out + (base + (long long)k * stride) * 8, v[k]);
}

// General fallback: 128-bit, predicated, no hints.
__global__ __launch_bounds__(512)
void embed_gather_general(const int* __restrict__ indices,
                          const float4* __restrict__ weight,
                          float4* __restrict__ out,
                          long long total_vec)   // float4 count
{
    const long long stride = (long long)gridDim.x * blockDim.x;
    const long long base   = (long long)blockIdx.x * blockDim.x + threadIdx.x;

    int idx[UNROLL];
#pragma unroll
    for (int k = 0; k < UNROLL; k++) {
        long long p = base + (long long)k * stride;
        idx[k] = (p < total_vec) ? __ldg(indices + (p >> 4)) : 0;
    }
    float4 v[UNROLL];
#pragma unroll
    for (int k = 0; k < UNROLL; k++) {
        long long p = base + (long long)k * stride;
        if (p < total_vec)
            v[k] = __ldg(weight + (long long)idx[k] * 16 + (p & 15));
    }
#pragma unroll
    for (int k = 0; k < UNROLL; k++) {
        long long p = base + (long long)k * stride;
        if (p < total_vec) __stcs(out + p, v[k]);
    }
}

extern "C" void kernel_launch(void* const* d_in, const int* in_sizes, int n_in,
                              void* d_out, int out_size)
{
    const int* indices  = (const int*)d_in[0];     // 819200 int32
    long long  num_rows = in_sizes[0];

    const int threads = 512;
    long long total_vec256 = num_rows * 8;                  // 6,553,600
    long long per_block    = (long long)threads * UNROLL;   // 4096

    if (total_vec256 % per_block == 0) {
        int blocks = (int)(total_vec256 / per_block);       // 1600
        embed_gather_exact<<<blocks, threads>>>(
            indices, (const uint32_t*)d_in[1], (uint32_t*)d_out);
    } else {
        long long total_vec = num_rows * 16;
        int blocks = (int)((total_vec + per_block - 1) / per_block);
        embed_gather_general<<<blocks, threads>>>(
            indices, (const float4*)d_in[1], (float4*)d_out, total_vec);
    }
}

// round 7
// speedup vs baseline: 1.0045x; 1.0045x over previous
#include <cuda_runtime.h>
#include <cstdint>

// Embedding gather: out[i, :] = weight[indices[i], :]
// 819200 rows x 64 fp32 = 256B/row. 8 threads cover one row with 256-bit ops.
// v7 = v5 (UNROLL=4, 512 thr, 256-bit evict_last gathers / evict_first stores)
// + __launch_bounds__(512, 2): raises the ptxas register budget to 64 so all
// four V8 gather results actually stay in flight (v5/v6 got squeezed to 32
// regs and ptxas serialized the "front-batched" loads).

static constexpr int UNROLL = 4;

struct V8 { uint32_t r[8]; };

__device__ __forceinline__ V8 ldg256_evict_last(const uint32_t* p) {
    V8 v;
    asm volatile("ld.global.nc.L2::evict_last.v8.b32 {%0,%1,%2,%3,%4,%5,%6,%7}, [%8];"
                 : "=r"(v.r[0]), "=r"(v.r[1]), "=r"(v.r[2]), "=r"(v.r[3]),
                   "=r"(v.r[4]), "=r"(v.r[5]), "=r"(v.r[6]), "=r"(v.r[7])
                 : "l"(p));
    return v;
}

__device__ __forceinline__ void stg256_evict_first(uint32_t* p, const V8& v) {
    asm volatile("st.global.L2::evict_first.v8.b32 [%0], {%1,%2,%3,%4,%5,%6,%7,%8};"
                 :: "l"(p),
                    "r"(v.r[0]), "r"(v.r[1]), "r"(v.r[2]), "r"(v.r[3]),
                    "r"(v.r[4]), "r"(v.r[5]), "r"(v.r[6]), "r"(v.r[7]));
}

// Exact path: total 32B-segments divisible by blockDim*UNROLL.
__global__ __launch_bounds__(512, 2)
void embed_gather_exact(const int* __restrict__ indices,
                        const uint32_t* __restrict__ weight,
                        uint32_t* __restrict__ out)
{
    const long long stride     = (long long)gridDim.x * blockDim.x; // mult of 8
    const long long base       = (long long)blockIdx.x * blockDim.x + threadIdx.x;
    const int       seg        = (int)(base & 7);      // 32B segment within row
    const long long row0       = base >> 3;
    const long long row_stride = stride >> 3;

    // Batch 1: independent index loads
    int idx[UNROLL];
#pragma unroll
    for (int k = 0; k < UNROLL; k++)
        idx[k] = __ldg(indices + row0 + (long long)k * row_stride);

    // Batch 2: 4 independent 256-bit gathers in flight per thread
    V8 v[UNROLL];
#pragma unroll
    for (int k = 0; k < UNROLL; k++)
        v[k] = ldg256_evict_last(weight + (long long)idx[k] * 64 + seg * 8);

    // Batch 3: 256-bit streaming stores, evict-first
#pragma unroll
    for (int k = 0; k < UNROLL; k++)
        stg256_evict_first(out + (base + (long long)k * stride) * 8, v[k]);
}

// General fallback: 128-bit, predicated, no hints.
__global__ __launch_bounds__(512, 2)
void embed_gather_general(const int* __restrict__ indices,
                          const float4* __restrict__ weight,
                          float4* __restrict__ out,
                          long long total_vec)   // float4 count
{
    const long long stride = (long long)gridDim.x * blockDim.x;
    const long long base   = (long long)blockIdx.x * blockDim.x + threadIdx.x;

    int idx[UNROLL];
#pragma unroll
    for (int k = 0; k < UNROLL; k++) {
        long long p = base + (long long)k * stride;
        idx[k] = (p < total_vec) ? __ldg(indices + (p >> 4)) : 0;
    }
    float4 v[UNROLL];
#pragma unroll
    for (int k = 0; k < UNROLL; k++) {
        long long p = base + (long long)k * stride;
        if (p < total_vec)
            v[k] = __ldg(weight + (long long)idx[k] * 16 + (p & 15));
    }
#pragma unroll
    for (int k = 0; k < UNROLL; k++) {
        long long p = base + (long long)k * stride;
        if (p < total_vec) __stcs(out + p, v[k]);
    }
}

extern "C" void kernel_launch(void* const* d_in, const int* in_sizes, int n_in,
                              void* d_out, int out_size)
{
    const int* indices  = (const int*)d_in[0];     // 819200 int32
    long long  num_rows = in_sizes[0];

    const int threads = 512;
    long long total_vec256 = num_rows * 8;                  // 6,553,600
    long long per_block    = (long long)threads * UNROLL;   // 2048

    if (total_vec256 % per_block == 0) {
        int blocks = (int)(total_vec256 / per_block);       // 3200
        embed_gather_exact<<<blocks, threads>>>(
            indices, (const uint32_t*)d_in[1], (uint32_t*)d_out);
    } else {
        long long total_vec = num_rows * 16;
        int blocks = (int)((total_vec + per_block - 1) / per_block);
        embed_gather_general<<<blocks, threads>>>(
            indices, (const float4*)d_in[1], (float4*)d_out, total_vec);
    }
}

// round 8
// speedup vs baseline: 1.0086x; 1.0040x over previous
#include <cuda_runtime.h>
#include <cstdint>

// Embedding gather: out[i, :] = weight[indices[i], :]
// 819200 rows x 64 fp32 = 256B/row. 8 threads cover one row with 256-bit ops.
// v8 = v5 datapath (UNROLL=4, 256-bit evict_last gathers / evict_first stores)
// at the max-occupancy operating point: 256-thread blocks, 32 regs -> 8
// blocks/SM = 64 warps (100% theoretical occ). DRAM utilization on this
// random gather tracks total resident warps (v5/v6/v7 evidence), so max occ
// is the lever, not per-thread register MLP.

static constexpr int UNROLL = 4;

struct V8 { uint32_t r[8]; };

__device__ __forceinline__ V8 ldg256_evict_last(const uint32_t* p) {
    V8 v;
    asm volatile("ld.global.nc.L2::evict_last.v8.b32 {%0,%1,%2,%3,%4,%5,%6,%7}, [%8];"
                 : "=r"(v.r[0]), "=r"(v.r[1]), "=r"(v.r[2]), "=r"(v.r[3]),
                   "=r"(v.r[4]), "=r"(v.r[5]), "=r"(v.r[6]), "=r"(v.r[7])
                 : "l"(p));
    return v;
}

__device__ __forceinline__ void stg256_evict_first(uint32_t* p, const V8& v) {
    asm volatile("st.global.L2::evict_first.v8.b32 [%0], {%1,%2,%3,%4,%5,%6,%7,%8};"
                 :: "l"(p),
                    "r"(v.r[0]), "r"(v.r[1]), "r"(v.r[2]), "r"(v.r[3]),
                    "r"(v.r[4]), "r"(v.r[5]), "r"(v.r[6]), "r"(v.r[7]));
}

// Exact path: total 32B-segments divisible by blockDim*UNROLL.
__global__ __launch_bounds__(256)
void embed_gather_exact(const int* __restrict__ indices,
                        const uint32_t* __restrict__ weight,
                        uint32_t* __restrict__ out)
{
    const long long stride     = (long long)gridDim.x * blockDim.x; // mult of 8
    const long long base       = (long long)blockIdx.x * blockDim.x + threadIdx.x;
    const int       seg        = (int)(base & 7);      // 32B segment within row
    const long long row0       = base >> 3;
    const long long row_stride = stride >> 3;

    // Batch 1: independent index loads
    int idx[UNROLL];
#pragma unroll
    for (int k = 0; k < UNROLL; k++)
        idx[k] = __ldg(indices + row0 + (long long)k * row_stride);

    // Batch 2: independent 256-bit gathers; table lines biased to stay in L2
    V8 v[UNROLL];
#pragma unroll
    for (int k = 0; k < UNROLL; k++)
        v[k] = ldg256_evict_last(weight + (long long)idx[k] * 64 + seg * 8);

    // Batch 3: 256-bit streaming stores, evict-first (never re-read)
#pragma unroll
    for (int k = 0; k < UNROLL; k++)
        stg256_evict_first(out + (base + (long long)k * stride) * 8, v[k]);
}

// General fallback: 128-bit, predicated, no hints.
__global__ __launch_bounds__(256)
void embed_gather_general(const int* __restrict__ indices,
                          const float4* __restrict__ weight,
                          float4* __restrict__ out,
                          long long total_vec)   // float4 count
{
    const long long stride = (long long)gridDim.x * blockDim.x;
    const long long base   = (long long)blockIdx.x * blockDim.x + threadIdx.x;

    int idx[UNROLL];
#pragma unroll
    for (int k = 0; k < UNROLL; k++) {
        long long p = base + (long long)k * stride;
        idx[k] = (p < total_vec) ? __ldg(indices + (p >> 4)) : 0;
    }
    float4 v[UNROLL];
#pragma unroll
    for (int k = 0; k < UNROLL; k++) {
        long long p = base + (long long)k * stride;
        if (p < total_vec)
            v[k] = __ldg(weight + (long long)idx[k] * 16 + (p & 15));
    }
#pragma unroll
    for (int k = 0; k < UNROLL; k++) {
        long long p = base + (long long)k * stride;
        if (p < total_vec) __stcs(out + p, v[k]);
    }
}

extern "C" void kernel_launch(void* const* d_in, const int* in_sizes, int n_in,
                              void* d_out, int out_size)
{
    const int* indices  = (const int*)d_in[0];     // 819200 int32
    long long  num_rows = in_sizes[0];

    const int threads = 256;
    long long total_vec256 = num_rows * 8;                  // 6,553,600
    long long per_block    = (long long)threads * UNROLL;   // 1024

    if (total_vec256 % per_block == 0) {
        int blocks = (int)(total_vec256 / per_block);       // 6400
        embed_gather_exact<<<blocks, threads>>>(
            indices, (const uint32_t*)d_in[1], (uint32_t*)d_out);
    } else {
        long long total_vec = num_rows * 16;
        int blocks = (int)((total_vec + per_block - 1) / per_block);
        embed_gather_general<<<blocks, threads>>>(
            indices, (const float4*)d_in[1], (float4*)d_out, total_vec);
    }
}